// round 11
// baseline (speedup 1.0000x reference)
#include <cuda_runtime.h>
#include <cuda_bf16.h>
#include <cstdint>

// EmbeddingLoss via HMMA bf16 Gram with label one-hot channels folded into the
// GEMM (K=80): s' = s - 65536*[same] => max(s',0.5) = same ? 0.5 : max(s,0.5).
// V_b = G_b - 0.5*P^2 + P - sum_l |u_l|^2/cnt^2  (analytic tail from class sums).
// Tiles stored PRE-TILED in gmem (contiguous 20KB per 128x80 tile, XOR swizzle
// baked in) so cp.async copies stay contiguous (fixes R8's L2 blowup).
// Persistent CTAs + double buffer. Epilogue: FMAX + FMA per element, no labels.

namespace {
constexpr int NPIX  = 4096;
constexpr int CH    = 64;
constexpr int CHN   = 80;                         // 64 emb + 16 one-hot
constexpr int BATCH = 4;
constexpr int BM    = 128;
constexpr int TILES = NPIX / BM;                  // 32
constexpr int TRI   = TILES * (TILES + 1) / 2;    // 528
constexpr int NTILES = BATCH * TRI;               // 2112
constexpr int PGRID  = 296;
constexpr int MAXT   = (NTILES + PGRID - 1) / PGRID;  // 8
constexpr int SSTR   = CHN * 2;                   // 160B row stride
constexpr int TILE_BYTES = BM * SSTR;             // 20480
constexpr int CONV_BLOCKS = BATCH * NPIX * (CHN / 2) / 256;  // 2560
constexpr int CLS_PER_B = 16;
constexpr int CLS_BLOCKS = BATCH * CLS_PER_B;     // 64
constexpr float MARGIN = 0.5f;
}

__device__ double   g_acc;
__device__ unsigned g_done;
__device__ float    g_pw[BATCH * NPIX];
__device__ int      g_cnt[BATCH * 16];
__device__ float    g_cls[BATCH * 16 * CH];       // zero at load; re-zeroed by finalize
__device__ __align__(16) __nv_bfloat16 g_tileA[BATCH * TILES * BM * CHN];
__device__ __align__(16) __nv_bfloat16 g_tileB[BATCH * TILES * BM * CHN];

__device__ __forceinline__ uint32_t smem_u32(const void* p) {
    uint32_t a;
    asm("{ .reg .u64 t; cvta.to.shared.u64 t, %1; cvt.u32.u64 %0, t; }"
        : "=r"(a) : "l"(p));
    return a;
}
__device__ __forceinline__ void ldsm_x4(uint32_t& r0, uint32_t& r1,
                                        uint32_t& r2, uint32_t& r3, uint32_t a) {
    asm volatile("ldmatrix.sync.aligned.m8n8.x4.shared.b16 {%0,%1,%2,%3}, [%4];"
                 : "=r"(r0), "=r"(r1), "=r"(r2), "=r"(r3) : "r"(a));
}
__device__ __forceinline__ void mma16816(float* d, const uint32_t* a,
                                         uint32_t b0, uint32_t b1) {
    asm volatile(
        "mma.sync.aligned.m16n8k16.row.col.f32.bf16.bf16.f32 "
        "{%0,%1,%2,%3}, {%4,%5,%6,%7}, {%8,%9}, {%0,%1,%2,%3};"
        : "+f"(d[0]), "+f"(d[1]), "+f"(d[2]), "+f"(d[3])
        : "r"(a[0]), "r"(a[1]), "r"(a[2]), "r"(a[3]), "r"(b0), "r"(b1));
}
__device__ __forceinline__ void cp16(uint32_t s, const void* g) {
    asm volatile("cp.async.cg.shared.global [%0], [%1], 16;" :: "r"(s), "l"(g));
}

// ---------------- K1: tiled conv (+one-hot) + hist + class sums -------------
__global__ __launch_bounds__(256) void prep_conv_kernel(const float* __restrict__ emb,
                                                        const int* __restrict__ lab) {
    const int bx = blockIdx.x, tid = threadIdx.x;
    if (bx < CONV_BLOCKS) {
        // one u32 slot of one row, written into the pre-tiled 160B-stride layout
        const int idx  = bx * 256 + tid;
        const int row  = idx / 40;              // global row: b*4096 + n
        const int slot = idx - row * 40;        // u32 slot 0..39
        const int R    = row & (BM - 1);        // row within tile
        const size_t tbase = (size_t)(row >> 7) * (TILE_BYTES / 4) ;  // u32 units
        uint32_t* dA = reinterpret_cast<uint32_t*>(g_tileA) + tbase + R * (SSTR / 4);
        uint32_t* dB = reinterpret_cast<uint32_t*>(g_tileB) + tbase + R * (SSTR / 4);
        if (slot < 32) {
            const int c   = slot >> 2;           // 16B chunk 0..7
            const int sub = slot & 3;
            const int off = (((c ^ (R & 7)) << 4) + (sub << 2)) >> 2;  // u32 units
            const float2 v = reinterpret_cast<const float2*>(emb)[(size_t)row * 32 + slot];
            __nv_bfloat162 p(__float2bfloat16(v.x), __float2bfloat16(v.y));
            const uint32_t u = *reinterpret_cast<uint32_t*>(&p);
            dA[off] = u;
            dB[off] = u;
        } else {
            const int s8 = slot - 32;            // one-hot u32 0..7 -> channels 2s8,2s8+1
            const int off = (128 >> 2) + s8;     // bytes 128.. unswizzled
            const int l  = lab[row] & 15;
            const int c0 = 2 * s8;
            __nv_bfloat162 pa(__float2bfloat16(c0 == l ?  256.0f : 0.0f),
                              __float2bfloat16(c0 + 1 == l ?  256.0f : 0.0f));
            __nv_bfloat162 pb(__float2bfloat16(c0 == l ? -256.0f : 0.0f),
                              __float2bfloat16(c0 + 1 == l ? -256.0f : 0.0f));
            dA[off] = *reinterpret_cast<uint32_t*>(&pa);
            dB[off] = *reinterpret_cast<uint32_t*>(&pb);
        }
    } else if (bx < CONV_BLOCKS + BATCH) {
        // per-batch label histogram -> counts + per-pixel weights
        __shared__ int hist[8][16];
        const int b = bx - CONV_BLOCKS;
        const int w = tid >> 5;
        if (tid < 128) hist[tid >> 4][tid & 15] = 0;
        if (b == 0 && tid == 0) { g_acc = 0.0; g_done = 0u; }
        __syncthreads();
        const int* L = lab + b * NPIX;
        for (int n = tid; n < NPIX; n += 256) atomicAdd(&hist[w][L[n] & 15], 1);
        __syncthreads();
        if (tid < 16) {
            int s = 0;
#pragma unroll
            for (int i = 0; i < 8; i++) s += hist[i][tid];
            hist[0][tid] = s;
            g_cnt[b * 16 + tid] = s;
        }
        __syncthreads();
        for (int n = tid; n < NPIX; n += 256)
            g_pw[b * NPIX + n] = 1.0f / (float)hist[0][L[n] & 15];
    } else {
        // per-class embedding sums over a 256-row slice (fp32, exact tail)
        __shared__ float us[4][16][CH];   // 16KB
        __shared__ int   labs[256];
        const int cb = bx - CONV_BLOCKS - BATCH;
        const int b  = cb / CLS_PER_B;
        const int r0 = (cb % CLS_PER_B) * 256;
        for (int i = tid; i < 4 * 16 * CH; i += 256)
            (&us[0][0][0])[i] = 0.0f;
        labs[tid] = lab[b * NPIX + r0 + tid];
        __syncthreads();
        const int ch = tid & 63, g = tid >> 6;
        const float* Eb = emb + ((size_t)(b * NPIX + r0 + g * 64)) * CH + ch;
#pragma unroll 4
        for (int k = 0; k < 64; k++)
            us[g][labs[g * 64 + k] & 15][ch] += Eb[(size_t)k * CH];
        __syncthreads();
        for (int i = tid; i < 16 * CH; i += 256) {
            const float v = us[0][0][i] + us[1][0][i] + us[2][0][i] + us[3][0][i];
            if (v != 0.0f) atomicAdd(&g_cls[b * 16 * CH + i], v);
        }
    }
}

// ---------------- K2: persistent HMMA Gram (K=80), label-free epilogue ------
__global__ __launch_bounds__(256, 2) void gram_kernel(float* __restrict__ out) {
    __shared__ __align__(16) char Asm[2][TILE_BYTES];   // 2 x 20KB
    __shared__ __align__(16) char Bsm[2][TILE_BYTES];   // 2 x 20KB
    __shared__ float prowf[2][BM], pcol[2][BM];         // prowf = (diag?1:2)*pw
    __shared__ int   tinfo[MAXT];
    __shared__ float red[8];
    __shared__ int   lastflag;
    __shared__ float sSum, sP[BATCH];

    const int tid = threadIdx.x;
    const int wid = tid >> 5;
    const int lid = tid & 31;
    const int wr  = wid & 1;
    const int wc  = wid >> 1;
    const int bid = blockIdx.x;

    const uint32_t aS[2] = { smem_u32(Asm[0]), smem_u32(Asm[1]) };
    const uint32_t bS[2] = { smem_u32(Bsm[0]), smem_u32(Bsm[1]) };

    const int nt = (NTILES - bid + PGRID - 1) / PGRID;

    if (tid == 0) {
        lastflag = 0;
        for (int k = 0; k < nt; k++) {
            const int idx = bid + k * PGRID;
            const int b = idx / TRI;
            int t = idx - b * TRI;
            int u = 0;
            while (t >= TILES - u) { t -= TILES - u; u++; }
            tinfo[k] = (b << 12) | (u << 6) | (u + t);
        }
    }
    if (tid < BATCH) sP[tid] = 0.0f;
    if (tid == 1) sSum = 0.0f;
    __syncthreads();

    auto issue = [&](int k, int par) {
        const int inf = tinfo[k];
        const int b = inf >> 12, ti = (inf >> 6) & 63, tj = inf & 63;
        const char* srcA = (const char*)g_tileA + (size_t)(b * TILES + ti) * TILE_BYTES;
        const char* srcB = (const char*)g_tileB + (size_t)(b * TILES + tj) * TILE_BYTES;
#pragma unroll
        for (int p = 0; p < 5; p++) {
            const int o = (tid + 256 * p) * 16;
            cp16(aS[par] + o, srcA + o);
            cp16(bS[par] + o, srcB + o);
        }
        if (tid < BM) {
            prowf[par][tid] = (ti == tj ? 1.0f : 2.0f) * g_pw[b * NPIX + ti * BM + tid];
        } else {
            const int u = tid - BM;
            pcol[par][u] = g_pw[b * NPIX + tj * BM + u];
        }
        asm volatile("cp.async.commit_group;" ::: "memory");
    };

    float tsum = 0.0f;
    issue(0, 0);

    int par = 0;
    for (int k = 0; k < nt; k++) {
        const bool has_next = (k + 1 < nt);
        if (has_next) issue(k + 1, par ^ 1);
        if (has_next) asm volatile("cp.async.wait_group 1;" ::: "memory");
        else          asm volatile("cp.async.wait_group 0;" ::: "memory");
        __syncthreads();

        float acc[4][4][4];
#pragma unroll
        for (int i = 0; i < 4; i++)
#pragma unroll
            for (int j = 0; j < 4; j++)
#pragma unroll
                for (int e = 0; e < 4; e++) acc[i][j][e] = 0.0f;

        const int aR = 64 * wr + (lid & 15);
        const int bR = 32 * wc + (lid & 15);
        const int hi = lid >> 4;
        const int x7 = lid & 7;                 // row-XOR term (row-block invariant)
        uint32_t aRow[4], bRow[2];
#pragma unroll
        for (int i = 0; i < 4; i++) aRow[i] = aS[par] + (aR + 16 * i) * SSTR;
#pragma unroll
        for (int p = 0; p < 2; p++) bRow[p] = bS[par] + (bR + 16 * p) * SSTR;

#pragma unroll
        for (int ks = 0; ks < 5; ks++) {        // K = 80: 4 emb steps + 1 one-hot
            const uint32_t off = (ks < 4)
                ? (uint32_t)(((ks * 2 + hi) ^ x7) << 4)
                : (uint32_t)((8 + hi) << 4);
            uint32_t a[4][4];
#pragma unroll
            for (int i = 0; i < 4; i++)
                ldsm_x4(a[i][0], a[i][1], a[i][2], a[i][3], aRow[i] + off);
            uint32_t bb[2][4];
#pragma unroll
            for (int p = 0; p < 2; p++)
                ldsm_x4(bb[p][0], bb[p][1], bb[p][2], bb[p][3], bRow[p] + off);
#pragma unroll
            for (int i = 0; i < 4; i++)
#pragma unroll
                for (int j = 0; j < 4; j++)
                    mma16816(acc[i][j], a[i], bb[j >> 1][j & 1], bb[j >> 1][(j & 1) + 2]);
        }

        // -------- epilogue: tsum += pn * sum_cols pc * max(s', 0.5) ----------
        const int gr = lid >> 2;
        const int qc = (lid & 3) * 2;
        float pcv[8];
#pragma unroll
        for (int j = 0; j < 4; j++) {
            const int cl = 32 * wc + 8 * j + qc;
            pcv[2 * j]     = pcol[par][cl];
            pcv[2 * j + 1] = pcol[par][cl + 1];
        }
#pragma unroll
        for (int i = 0; i < 4; i++) {
            const int rl0 = 64 * wr + 16 * i + gr, rl1 = rl0 + 8;
            float rs0 = 0.0f, rs1 = 0.0f;
#pragma unroll
            for (int j = 0; j < 4; j++) {
                rs0 = fmaf(fmaxf(acc[i][j][0], MARGIN), pcv[2 * j],     rs0);
                rs0 = fmaf(fmaxf(acc[i][j][1], MARGIN), pcv[2 * j + 1], rs0);
                rs1 = fmaf(fmaxf(acc[i][j][2], MARGIN), pcv[2 * j],     rs1);
                rs1 = fmaf(fmaxf(acc[i][j][3], MARGIN), pcv[2 * j + 1], rs1);
            }
            tsum = fmaf(rs0, prowf[par][rl0], tsum);
            tsum = fmaf(rs1, prowf[par][rl1], tsum);
        }
        __syncthreads();
        par ^= 1;
    }

    // -------- block reduce + last-block analytic tail ------------------------
#pragma unroll
    for (int o = 16; o > 0; o >>= 1)
        tsum += __shfl_xor_sync(0xffffffffu, tsum, o);
    if (lid == 0) red[wid] = tsum;
    __syncthreads();
    if (tid == 0) {
        float bsum = 0.0f;
#pragma unroll
        for (int wv = 0; wv < 8; wv++) bsum += red[wv];
        atomicAdd(&g_acc, (double)bsum);
        __threadfence();
        const unsigned done = atomicAdd(&g_done, 1u);
        if (done == (unsigned)(PGRID - 1)) lastflag = 1;
    }
    __syncthreads();

    if (lastflag) {
        __threadfence();
        if (tid < BATCH * 16) {
            const int bb_ = tid >> 4;
            const int cnt = g_cnt[tid];
            if (cnt > 0) {
                float dot = 0.0f;
                const float* u = g_cls + tid * CH;
#pragma unroll 8
                for (int c = 0; c < CH; c++) dot = fmaf(u[c], u[c], dot);
                const float inv = 1.0f / ((float)cnt * (float)cnt);
                atomicAdd(&sSum, 1.0f - dot * inv);   // contributes P - sum|u|^2/cnt^2
                atomicAdd(&sP[bb_], 1.0f);
            }
        }
        __syncthreads();
        if (tid == 0) {
            double extra = (double)sSum;
            for (int bb_ = 0; bb_ < BATCH; bb_++) {
                const double P = (double)sP[bb_];
                extra -= 0.5 * P * P;                 // - 0.5 * P^2
            }
            out[0] = (float)((*((volatile double*)&g_acc) + extra) * (double)NPIX);
        }
        for (int i = tid; i < BATCH * 16 * CH; i += 256) g_cls[i] = 0.0f;
    }
}

extern "C" void kernel_launch(void* const* d_in, const int* in_sizes, int n_in,
                              void* d_out, int out_size) {
    const float* emb = (const float*)d_in[0];
    const int*   lab = (const int*)d_in[1];
    float* out = (float*)d_out;

    prep_conv_kernel<<<CONV_BLOCKS + BATCH + CLS_BLOCKS, 256>>>(emb, lab);
    gram_kernel<<<PGRID, 256>>>(out);
}

// round 12
// speedup vs baseline: 1.2366x; 1.2366x over previous
#include <cuda_runtime.h>
#include <cuda_bf16.h>
#include <cstdint>

// EmbeddingLoss: ONE persistent kernel. Phase A: fp32->bf16 swizzled convert +
// label histogram. Grid barrier. Phase B: per-pixel weights. Grid barrier.
// Phase C: R10-proven HMMA Gram (3-stage cp.async ring, one barrier/tile,
// 128x128 upper-tri tiles, x2 off-diag) + last-block finalize & state reset.
// All 296 blocks co-resident (2/SM) -> spin barriers are deadlock-free.

namespace {
constexpr int NPIX  = 4096;
constexpr int CH    = 64;
constexpr int BATCH = 4;
constexpr int BM    = 128;
constexpr int TILES = NPIX / BM;                 // 32
constexpr int TRI   = TILES * (TILES + 1) / 2;   // 528
constexpr int NTILES = BATCH * TRI;              // 2112
constexpr int PGRID  = 296;                      // 2 CTAs/SM, all resident
constexpr int MAXT   = (NTILES + PGRID - 1) / PGRID;  // 8
constexpr int NQ     = BATCH * NPIX * CH / 4;    // 262144 float4 conv units
constexpr float MARGIN = 0.5f;
}

__device__ double   g_acc;       // zero-init at load; reset by last block each run
__device__ unsigned g_done;
__device__ unsigned g_bar;       // grid-barrier arrival counter (monotonic per run)
__device__ int      g_cnt[BATCH * 16];
__device__ float    g_pw[BATCH * NPIX];
__device__ __nv_bfloat16 g_ebf[BATCH * NPIX * CH];  // bf16, per-row XOR-swizzled

__device__ __forceinline__ uint32_t smem_u32(const void* p) {
    uint32_t a;
    asm("{ .reg .u64 t; cvta.to.shared.u64 t, %1; cvt.u32.u64 %0, t; }"
        : "=r"(a) : "l"(p));
    return a;
}
__device__ __forceinline__ void ldsm_x4(uint32_t& r0, uint32_t& r1,
                                        uint32_t& r2, uint32_t& r3, uint32_t a) {
    asm volatile("ldmatrix.sync.aligned.m8n8.x4.shared.b16 {%0,%1,%2,%3}, [%4];"
                 : "=r"(r0), "=r"(r1), "=r"(r2), "=r"(r3) : "r"(a));
}
__device__ __forceinline__ void mma16816(float* d, const uint32_t* a,
                                         uint32_t b0, uint32_t b1) {
    asm volatile(
        "mma.sync.aligned.m16n8k16.row.col.f32.bf16.bf16.f32 "
        "{%0,%1,%2,%3}, {%4,%5,%6,%7}, {%8,%9}, {%0,%1,%2,%3};"
        : "+f"(d[0]), "+f"(d[1]), "+f"(d[2]), "+f"(d[3])
        : "r"(a[0]), "r"(a[1]), "r"(a[2]), "r"(a[3]), "r"(b0), "r"(b1));
}
__device__ __forceinline__ uint32_t sw_off(int R, int c) {
    return (uint32_t)(R * 128 + ((c ^ (R & 7)) << 4));
}
__device__ __forceinline__ void cp16(uint32_t s, const void* g) {
    asm volatile("cp.async.cg.shared.global [%0], [%1], 16;" :: "r"(s), "l"(g));
}

// Grid barrier: all PGRID blocks co-resident. `target` = PGRID * phase_index.
__device__ __forceinline__ void grid_barrier(int tid, unsigned target) {
    __syncthreads();
    if (tid == 0) {
        __threadfence();
        atomicAdd(&g_bar, 1u);
        while (*((volatile unsigned*)&g_bar) < target) { }
    }
    __syncthreads();
    __threadfence();
}

__global__ __launch_bounds__(256, 2) void fused_kernel(const float* __restrict__ emb,
                                                       const int* __restrict__ lab,
                                                       float* __restrict__ out) {
    __shared__ __align__(16) __nv_bfloat16 Asm[3][BM * CH];   // 3 x 16KB
    __shared__ __align__(16) __nv_bfloat16 Bsm[3][BM * CH];   // 3 x 16KB
    __shared__ int   lrow[3][BM], lcol[3][BM];
    __shared__ float prowf[3][BM], pcol[3][BM];
    __shared__ int   tinfo[MAXT];
    __shared__ float red[8];
    __shared__ int   hist[16];

    const int tid = threadIdx.x;
    const int wid = tid >> 5;
    const int lid = tid & 31;
    const int wr  = wid & 1;
    const int wc  = wid >> 1;
    const int bid = blockIdx.x;

    // ================= Phase A: convert + histogram =========================
    // conv: grid-stride over 262144 float4 units
    for (int q = bid * 256 + tid; q < NQ; q += PGRID * 256) {
        const int c4 = (q & 15) * 4;
        const int n  = (q >> 4) & (NPIX - 1);
        const float4 v = reinterpret_cast<const float4*>(emb)[q];
        const int chunk = c4 >> 3;
        const int dcol  = ((chunk ^ (n & 7)) << 3) + (c4 & 7);
        __nv_bfloat162* d2 = reinterpret_cast<__nv_bfloat162*>(
            g_ebf + ((size_t)(q >> 4)) * CH + dcol);
        d2[0] = __nv_bfloat162(__float2bfloat16(v.x), __float2bfloat16(v.y));
        d2[1] = __nv_bfloat162(__float2bfloat16(v.z), __float2bfloat16(v.w));
    }
    // hist: first 64 blocks each cover a 256-label slice (4*4096/256 = 64)
    if (bid < 64) {
        if (tid < 16) hist[tid] = 0;
        __syncthreads();
        const int b  = bid >> 4;            // 16 blocks per batch
        const int p0 = (bid & 15) * 256;
        atomicAdd(&hist[lab[b * NPIX + p0 + tid] & 15], 1);
        __syncthreads();
        if (tid < 16 && hist[tid] > 0) atomicAdd(&g_cnt[b * 16 + tid], hist[tid]);
    }
    grid_barrier(tid, PGRID);

    // ================= Phase B: per-pixel weights ===========================
    for (int n = bid * 256 + tid; n < BATCH * NPIX; n += PGRID * 256) {
        const int b = n >> 12;
        g_pw[n] = 1.0f / (float)g_cnt[b * 16 + (lab[n] & 15)];
    }
    grid_barrier(tid, 2u * PGRID);

    // ================= Phase C: HMMA Gram (R10 verbatim) ====================
    const uint32_t aS[3] = { smem_u32(Asm[0]), smem_u32(Asm[1]), smem_u32(Asm[2]) };
    const uint32_t bS[3] = { smem_u32(Bsm[0]), smem_u32(Bsm[1]), smem_u32(Bsm[2]) };

    const int nt = (NTILES - bid + PGRID - 1) / PGRID;

    if (tid == 0) {
        for (int k = 0; k < nt; k++) {
            const int idx = bid + k * PGRID;
            const int b = idx / TRI;
            int t = idx - b * TRI;
            int u = 0;
            while (t >= TILES - u) { t -= TILES - u; u++; }
            tinfo[k] = (b << 12) | (u << 6) | (u + t);
        }
    }
    __syncthreads();

    auto issue = [&](int k, int buf) {
        const int inf = tinfo[k];
        const int b = inf >> 12, ti = (inf >> 6) & 63, tj = inf & 63;
        const int row0 = ti * BM, col0 = tj * BM;
        const char* srcA = (const char*)(g_ebf + ((size_t)(b * NPIX + row0)) * CH);
        const char* srcB = (const char*)(g_ebf + ((size_t)(b * NPIX + col0)) * CH);
#pragma unroll
        for (int p = 0; p < 4; p++) {
            const int o = (tid + 256 * p) * 16;
            cp16(aS[buf] + o, srcA + o);
            cp16(bS[buf] + o, srcB + o);
        }
        if (tid < BM) {
            lrow[buf][tid]  = lab[b * NPIX + row0 + tid];
            prowf[buf][tid] = (ti == tj ? 1.0f : 2.0f) * g_pw[b * NPIX + row0 + tid];
        } else {
            const int u = tid - BM;
            lcol[buf][u] = lab[b * NPIX + col0 + u];
            pcol[buf][u] = g_pw[b * NPIX + col0 + u];
        }
        asm volatile("cp.async.commit_group;" ::: "memory");
    };

    float tsum = 0.0f;
    issue(0, 0);
    if (nt > 1) issue(1, 1);

    int buf = 0, nbuf = 2;
    for (int k = 0; k < nt; k++) {
        if (k + 1 < nt) asm volatile("cp.async.wait_group 1;" ::: "memory");
        else            asm volatile("cp.async.wait_group 0;" ::: "memory");
        __syncthreads();
        if (k + 2 < nt) issue(k + 2, nbuf);

        const int inf = tinfo[k];
        const int ti = (inf >> 6) & 63, tj = inf & 63;
        const bool diag = (ti == tj);

        const uint32_t a_base = aS[buf];
        const uint32_t b_base = bS[buf];

        float acc[4][4][4];
#pragma unroll
        for (int i = 0; i < 4; i++)
#pragma unroll
            for (int j = 0; j < 4; j++)
#pragma unroll
                for (int e = 0; e < 4; e++) acc[i][j][e] = 0.0f;

        const int aR = 64 * wr + (lid & 15);
        const int bR = 32 * wc + (lid & 15);
        const int hi = lid >> 4;

#pragma unroll
        for (int ks = 0; ks < 4; ks++) {
            const int ck = ks * 2 + hi;
            uint32_t a[4][4];
#pragma unroll
            for (int i = 0; i < 4; i++) {
                const int R = aR + 16 * i;
                ldsm_x4(a[i][0], a[i][1], a[i][2], a[i][3], a_base + sw_off(R, ck));
            }
            uint32_t bb[2][4];
#pragma unroll
            for (int p = 0; p < 2; p++) {
                const int R = bR + 16 * p;
                ldsm_x4(bb[p][0], bb[p][1], bb[p][2], bb[p][3], b_base + sw_off(R, ck));
            }
#pragma unroll
            for (int i = 0; i < 4; i++)
#pragma unroll
                for (int j = 0; j < 4; j++)
                    mma16816(acc[i][j], a[i], bb[j >> 1][j & 1], bb[j >> 1][(j & 1) + 2]);
        }

        const int gr = lid >> 2;
        const int qc = (lid & 3) * 2;
        if (!diag) {
#pragma unroll
            for (int i = 0; i < 4; i++) {
                const int rl0 = 64 * wr + 16 * i + gr, rl1 = rl0 + 8;
                const int  ln0 = lrow[buf][rl0], ln1 = lrow[buf][rl1];
                float rs0 = 0.0f, rs1 = 0.0f;
#pragma unroll
                for (int j = 0; j < 4; j++) {
                    const int cl = 32 * wc + 8 * j + qc;
                    const int  lc0 = lcol[buf][cl],  lc1 = lcol[buf][cl + 1];
                    const float pc0 = pcol[buf][cl], pc1 = pcol[buf][cl + 1];
                    const float s0 = acc[i][j][0], s1 = acc[i][j][1];
                    const float s2 = acc[i][j][2], s3 = acc[i][j][3];
                    const float v0 = (ln0 == lc0) ? (1.0f - s0) : fmaxf(s0 - MARGIN, 0.0f);
                    const float v1 = (ln0 == lc1) ? (1.0f - s1) : fmaxf(s1 - MARGIN, 0.0f);
                    const float v2 = (ln1 == lc0) ? (1.0f - s2) : fmaxf(s2 - MARGIN, 0.0f);
                    const float v3 = (ln1 == lc1) ? (1.0f - s3) : fmaxf(s3 - MARGIN, 0.0f);
                    rs0 = fmaf(v0, pc0, rs0); rs0 = fmaf(v1, pc1, rs0);
                    rs1 = fmaf(v2, pc0, rs1); rs1 = fmaf(v3, pc1, rs1);
                }
                tsum = fmaf(rs0, prowf[buf][rl0], tsum);
                tsum = fmaf(rs1, prowf[buf][rl1], tsum);
            }
        } else {
#pragma unroll
            for (int i = 0; i < 4; i++) {
#pragma unroll
                for (int j = 0; j < 4; j++) {
                    const int cl = 32 * wc + 8 * j + qc;
#pragma unroll
                    for (int e = 0; e < 4; e++) {
                        const int rl = 64 * wr + 16 * i + gr + ((e >> 1) << 3);
                        const int cc = cl + (e & 1);
                        const float s = acc[i][j][e];
                        const float v = (lrow[buf][rl] == lcol[buf][cc])
                                          ? (1.0f - s) : fmaxf(s - MARGIN, 0.0f);
                        float w = 2.0f * prowf[buf][rl] * pcol[buf][cc];
                        if (cc == rl)     w *= 0.5f;
                        else if (cc < rl) w = 0.0f;
                        tsum = fmaf(v, w, tsum);
                    }
                }
            }
        }
        buf  = (buf  == 2) ? 0 : buf + 1;
        nbuf = (nbuf == 2) ? 0 : nbuf + 1;
    }

    // ---- block reduce; last block finalizes and resets state for next replay
#pragma unroll
    for (int o = 16; o > 0; o >>= 1)
        tsum += __shfl_xor_sync(0xffffffffu, tsum, o);
    if (lid == 0) red[wid] = tsum;
    __syncthreads();
    if (tid == 0) {
        float bsum = 0.0f;
#pragma unroll
        for (int wv = 0; wv < 8; wv++) bsum += red[wv];
        atomicAdd(&g_acc, (double)bsum);
        __threadfence();
        const unsigned done = atomicAdd(&g_done, 1u);
        if (done == (unsigned)(PGRID - 1)) {
            __threadfence();
            out[0] = (float)(*((volatile double*)&g_acc) * (double)NPIX);
            // reset device state for the next graph replay
            g_acc  = 0.0;
            g_done = 0u;
            g_bar  = 0u;
#pragma unroll
            for (int i = 0; i < BATCH * 16; i++) g_cnt[i] = 0;
            __threadfence();
        }
    }
}

extern "C" void kernel_launch(void* const* d_in, const int* in_sizes, int n_in,
                              void* d_out, int out_size) {
    const float* emb = (const float*)d_in[0];
    const int*   lab = (const int*)d_in[1];
    float* out = (float*)d_out;

    fused_kernel<<<PGRID, 256>>>(emb, lab, out);
}

// round 13
// speedup vs baseline: 1.2595x; 1.0185x over previous
#include <cuda_runtime.h>
#include <cuda_bf16.h>
#include <cstdint>

// EmbeddingLoss: ONE persistent kernel, single grid barrier.
// Phase A: label histogram (first 64 blocks) + fp32->bf16 swizzled convert
//          (all blocks, grid-stride). Grid barrier.
// Then each block builds a 64-entry per-class weight table in smem
// (w[b][l] = 1/cnt, bit-identical to prior g_pw values) and runs the
// R10-proven HMMA Gram: 3-stage cp.async ring, one __syncthreads per tile,
// 128x128 upper-tri tiles (x2 off-diag), per-block reduce, last-block finalize.

namespace {
constexpr int NPIX  = 4096;
constexpr int CH    = 64;
constexpr int BATCH = 4;
constexpr int BM    = 128;
constexpr int TILES = NPIX / BM;                 // 32
constexpr int TRI   = TILES * (TILES + 1) / 2;   // 528
constexpr int NTILES = BATCH * TRI;              // 2112
constexpr int PGRID  = 296;                      // 2 CTAs/SM, all resident
constexpr int MAXT   = (NTILES + PGRID - 1) / PGRID;  // 8
constexpr int NQ     = BATCH * NPIX * CH / 4;    // 262144 float4 conv units
constexpr float MARGIN = 0.5f;
}

__device__ double   g_acc;       // zero-init at load; reset by last block
__device__ unsigned g_done;
__device__ unsigned g_bar;
__device__ int      g_cnt[BATCH * 16];
__device__ __nv_bfloat16 g_ebf[BATCH * NPIX * CH];  // bf16, per-row XOR-swizzled

__device__ __forceinline__ uint32_t smem_u32(const void* p) {
    uint32_t a;
    asm("{ .reg .u64 t; cvta.to.shared.u64 t, %1; cvt.u32.u64 %0, t; }"
        : "=r"(a) : "l"(p));
    return a;
}
__device__ __forceinline__ void ldsm_x4(uint32_t& r0, uint32_t& r1,
                                        uint32_t& r2, uint32_t& r3, uint32_t a) {
    asm volatile("ldmatrix.sync.aligned.m8n8.x4.shared.b16 {%0,%1,%2,%3}, [%4];"
                 : "=r"(r0), "=r"(r1), "=r"(r2), "=r"(r3) : "r"(a));
}
__device__ __forceinline__ void mma16816(float* d, const uint32_t* a,
                                         uint32_t b0, uint32_t b1) {
    asm volatile(
        "mma.sync.aligned.m16n8k16.row.col.f32.bf16.bf16.f32 "
        "{%0,%1,%2,%3}, {%4,%5,%6,%7}, {%8,%9}, {%0,%1,%2,%3};"
        : "+f"(d[0]), "+f"(d[1]), "+f"(d[2]), "+f"(d[3])
        : "r"(a[0]), "r"(a[1]), "r"(a[2]), "r"(a[3]), "r"(b0), "r"(b1));
}
__device__ __forceinline__ uint32_t sw_off(int R, int c) {
    return (uint32_t)(R * 128 + ((c ^ (R & 7)) << 4));
}
__device__ __forceinline__ void cp16(uint32_t s, const void* g) {
    asm volatile("cp.async.cg.shared.global [%0], [%1], 16;" :: "r"(s), "l"(g));
}

// Grid barrier: all PGRID blocks co-resident.
__device__ __forceinline__ void grid_barrier(int tid, unsigned target) {
    __syncthreads();
    if (tid == 0) {
        __threadfence();
        atomicAdd(&g_bar, 1u);
        while (*((volatile unsigned*)&g_bar) < target) { }
    }
    __syncthreads();
    __threadfence();
}

__global__ __launch_bounds__(256, 2) void fused_kernel(const float* __restrict__ emb,
                                                       const int* __restrict__ lab,
                                                       float* __restrict__ out) {
    __shared__ __align__(16) __nv_bfloat16 Asm[3][BM * CH];   // 3 x 16KB
    __shared__ __align__(16) __nv_bfloat16 Bsm[3][BM * CH];   // 3 x 16KB
    __shared__ int   lrow[3][BM], lcol[3][BM];
    __shared__ float prowf[3][BM], pcol[3][BM];
    __shared__ float swcls[BATCH * 16];   // per-class weights 1/cnt
    __shared__ int   tinfo[MAXT];
    __shared__ float red[8];
    __shared__ int   hist[16];

    const int tid = threadIdx.x;
    const int wid = tid >> 5;
    const int lid = tid & 31;
    const int wr  = wid & 1;
    const int wc  = wid >> 1;
    const int bid = blockIdx.x;

    // ================= Phase A: histogram first, then convert ================
    if (bid < 64) {
        if (tid < 16) hist[tid] = 0;
        __syncthreads();
        const int b  = bid >> 4;            // 16 blocks per batch, 256 labels each
        const int p0 = (bid & 15) * 256;
        atomicAdd(&hist[lab[b * NPIX + p0 + tid] & 15], 1);
        __syncthreads();
        if (tid < 16 && hist[tid] > 0) atomicAdd(&g_cnt[b * 16 + tid], hist[tid]);
    }
    for (int q = bid * 256 + tid; q < NQ; q += PGRID * 256) {
        const int c4 = (q & 15) * 4;
        const int n  = (q >> 4) & (NPIX - 1);
        const float4 v = reinterpret_cast<const float4*>(emb)[q];
        const int chunk = c4 >> 3;
        const int dcol  = ((chunk ^ (n & 7)) << 3) + (c4 & 7);
        __nv_bfloat162* d2 = reinterpret_cast<__nv_bfloat162*>(
            g_ebf + ((size_t)(q >> 4)) * CH + dcol);
        d2[0] = __nv_bfloat162(__float2bfloat16(v.x), __float2bfloat16(v.y));
        d2[1] = __nv_bfloat162(__float2bfloat16(v.z), __float2bfloat16(v.w));
    }
    grid_barrier(tid, PGRID);

    // per-class weight table (bit-identical to 1.0f/(float)cnt of prior rounds)
    if (tid < BATCH * 16) {
        const int c = g_cnt[tid];
        swcls[tid] = (c > 0) ? (1.0f / (float)c) : 0.0f;
    }
    __syncthreads();

    // ================= Phase C: HMMA Gram (R10 verbatim) ====================
    const uint32_t aS[3] = { smem_u32(Asm[0]), smem_u32(Asm[1]), smem_u32(Asm[2]) };
    const uint32_t bS[3] = { smem_u32(Bsm[0]), smem_u32(Bsm[1]), smem_u32(Bsm[2]) };

    const int nt = (NTILES - bid + PGRID - 1) / PGRID;

    if (tid == 0) {
        for (int k = 0; k < nt; k++) {
            const int idx = bid + k * PGRID;
            const int b = idx / TRI;
            int t = idx - b * TRI;
            int u = 0;
            while (t >= TILES - u) { t -= TILES - u; u++; }
            tinfo[k] = (b << 12) | (u << 6) | (u + t);
        }
    }
    __syncthreads();

    auto issue = [&](int k, int buf) {
        const int inf = tinfo[k];
        const int b = inf >> 12, ti = (inf >> 6) & 63, tj = inf & 63;
        const int row0 = ti * BM, col0 = tj * BM;
        const char* srcA = (const char*)(g_ebf + ((size_t)(b * NPIX + row0)) * CH);
        const char* srcB = (const char*)(g_ebf + ((size_t)(b * NPIX + col0)) * CH);
#pragma unroll
        for (int p = 0; p < 4; p++) {
            const int o = (tid + 256 * p) * 16;
            cp16(aS[buf] + o, srcA + o);
            cp16(bS[buf] + o, srcB + o);
        }
        if (tid < BM) {
            const int l = lab[b * NPIX + row0 + tid] & 15;
            lrow[buf][tid]  = l;
            prowf[buf][tid] = (ti == tj ? 1.0f : 2.0f) * swcls[(b << 4) + l];
        } else {
            const int u = tid - BM;
            const int l = lab[b * NPIX + col0 + u] & 15;
            lcol[buf][u] = l;
            pcol[buf][u] = swcls[(b << 4) + l];
        }
        asm volatile("cp.async.commit_group;" ::: "memory");
    };

    float tsum = 0.0f;
    issue(0, 0);
    if (nt > 1) issue(1, 1);

    int buf = 0, nbuf = 2;
    for (int k = 0; k < nt; k++) {
        if (k + 1 < nt) asm volatile("cp.async.wait_group 1;" ::: "memory");
        else            asm volatile("cp.async.wait_group 0;" ::: "memory");
        __syncthreads();
        if (k + 2 < nt) issue(k + 2, nbuf);

        const int inf = tinfo[k];
        const int ti = (inf >> 6) & 63, tj = inf & 63;
        const bool diag = (ti == tj);

        const uint32_t a_base = aS[buf];
        const uint32_t b_base = bS[buf];

        float acc[4][4][4];
#pragma unroll
        for (int i = 0; i < 4; i++)
#pragma unroll
            for (int j = 0; j < 4; j++)
#pragma unroll
                for (int e = 0; e < 4; e++) acc[i][j][e] = 0.0f;

        const int aR = 64 * wr + (lid & 15);
        const int bR = 32 * wc + (lid & 15);
        const int hi = lid >> 4;

#pragma unroll
        for (int ks = 0; ks < 4; ks++) {
            const int ck = ks * 2 + hi;
            uint32_t a[4][4];
#pragma unroll
            for (int i = 0; i < 4; i++) {
                const int R = aR + 16 * i;
                ldsm_x4(a[i][0], a[i][1], a[i][2], a[i][3], a_base + sw_off(R, ck));
            }
            uint32_t bb[2][4];
#pragma unroll
            for (int p = 0; p < 2; p++) {
                const int R = bR + 16 * p;
                ldsm_x4(bb[p][0], bb[p][1], bb[p][2], bb[p][3], b_base + sw_off(R, ck));
            }
#pragma unroll
            for (int i = 0; i < 4; i++)
#pragma unroll
                for (int j = 0; j < 4; j++)
                    mma16816(acc[i][j], a[i], bb[j >> 1][j & 1], bb[j >> 1][(j & 1) + 2]);
        }

        const int gr = lid >> 2;
        const int qc = (lid & 3) * 2;
        if (!diag) {
#pragma unroll
            for (int i = 0; i < 4; i++) {
                const int rl0 = 64 * wr + 16 * i + gr, rl1 = rl0 + 8;
                const int  ln0 = lrow[buf][rl0], ln1 = lrow[buf][rl1];
                float rs0 = 0.0f, rs1 = 0.0f;
#pragma unroll
                for (int j = 0; j < 4; j++) {
                    const int cl = 32 * wc + 8 * j + qc;
                    const int  lc0 = lcol[buf][cl],  lc1 = lcol[buf][cl + 1];
                    const float pc0 = pcol[buf][cl], pc1 = pcol[buf][cl + 1];
                    const float s0 = acc[i][j][0], s1 = acc[i][j][1];
                    const float s2 = acc[i][j][2], s3 = acc[i][j][3];
                    const float v0 = (ln0 == lc0) ? (1.0f - s0) : fmaxf(s0 - MARGIN, 0.0f);
                    const float v1 = (ln0 == lc1) ? (1.0f - s1) : fmaxf(s1 - MARGIN, 0.0f);
                    const float v2 = (ln1 == lc0) ? (1.0f - s2) : fmaxf(s2 - MARGIN, 0.0f);
                    const float v3 = (ln1 == lc1) ? (1.0f - s3) : fmaxf(s3 - MARGIN, 0.0f);
                    rs0 = fmaf(v0, pc0, rs0); rs0 = fmaf(v1, pc1, rs0);
                    rs1 = fmaf(v2, pc0, rs1); rs1 = fmaf(v3, pc1, rs1);
                }
                tsum = fmaf(rs0, prowf[buf][rl0], tsum);
                tsum = fmaf(rs1, prowf[buf][rl1], tsum);
            }
        } else {
#pragma unroll
            for (int i = 0; i < 4; i++) {
#pragma unroll
                for (int j = 0; j < 4; j++) {
                    const int cl = 32 * wc + 8 * j + qc;
#pragma unroll
                    for (int e = 0; e < 4; e++) {
                        const int rl = 64 * wr + 16 * i + gr + ((e >> 1) << 3);
                        const int cc = cl + (e & 1);
                        const float s = acc[i][j][e];
                        const float v = (lrow[buf][rl] == lcol[buf][cc])
                                          ? (1.0f - s) : fmaxf(s - MARGIN, 0.0f);
                        float w = 2.0f * prowf[buf][rl] * pcol[buf][cc];
                        if (cc == rl)     w *= 0.5f;
                        else if (cc < rl) w = 0.0f;
                        tsum = fmaf(v, w, tsum);
                    }
                }
            }
        }
        buf  = (buf  == 2) ? 0 : buf + 1;
        nbuf = (nbuf == 2) ? 0 : nbuf + 1;
    }

    // ---- block reduce; last block finalizes and resets state ---------------
#pragma unroll
    for (int o = 16; o > 0; o >>= 1)
        tsum += __shfl_xor_sync(0xffffffffu, tsum, o);
    if (lid == 0) red[wid] = tsum;
    __syncthreads();
    if (tid == 0) {
        float bsum = 0.0f;
#pragma unroll
        for (int wv = 0; wv < 8; wv++) bsum += red[wv];
        atomicAdd(&g_acc, (double)bsum);
        __threadfence();
        const unsigned done = atomicAdd(&g_done, 1u);
        if (done == (unsigned)(PGRID - 1)) {
            __threadfence();
            out[0] = (float)(*((volatile double*)&g_acc) * (double)NPIX);
            g_acc  = 0.0;
            g_done = 0u;
            g_bar  = 0u;
#pragma unroll
            for (int i = 0; i < BATCH * 16; i++) g_cnt[i] = 0;
            __threadfence();
        }
    }
}

extern "C" void kernel_launch(void* const* d_in, const int* in_sizes, int n_in,
                              void* d_out, int out_size) {
    const float* emb = (const float*)d_in[0];
    const int*   lab = (const int*)d_in[1];
    float* out = (float*)d_out;

    fused_kernel<<<PGRID, 256>>>(emb, lab, out);
}

// round 14
// speedup vs baseline: 1.3279x; 1.0543x over previous
#include <cuda_runtime.h>
#include <cuda_bf16.h>
#include <cstdint>

// EmbeddingLoss: ONE persistent kernel, single grid barrier.
// Phase A: fp32->bf16 swizzled convert (all blocks, grid-stride) + label
//          histogram on blocks 232..295 (the 7-tile blocks, keeping the
//          8-tile critical-path blocks prologue-free). Grid barrier.
// Then: per-class smem weight table + R10-proven HMMA Gram (3-stage cp.async
// ring, one __syncthreads/tile, 128x128 upper-tri tiles, x2 off-diag),
// per-block reduce, last-block finalize + state reset.

namespace {
constexpr int NPIX  = 4096;
constexpr int CH    = 64;
constexpr int BATCH = 4;
constexpr int BM    = 128;
constexpr int TILES = NPIX / BM;                 // 32
constexpr int TRI   = TILES * (TILES + 1) / 2;   // 528
constexpr int NTILES = BATCH * TRI;              // 2112
constexpr int PGRID  = 296;                      // 2 CTAs/SM, all resident
constexpr int MAXT   = (NTILES + PGRID - 1) / PGRID;  // 8
constexpr int NQ     = BATCH * NPIX * CH / 4;    // 262144 float4 conv units
constexpr int HIST0  = 232;                      // hist on blocks 232..295
constexpr float MARGIN = 0.5f;
}

__device__ double   g_acc;       // zero-init at load; reset by last block
__device__ unsigned g_done;
__device__ unsigned g_bar;
__device__ int      g_cnt[BATCH * 16];
__device__ __nv_bfloat16 g_ebf[BATCH * NPIX * CH];  // bf16, per-row XOR-swizzled

__device__ __forceinline__ uint32_t smem_u32(const void* p) {
    uint32_t a;
    asm("{ .reg .u64 t; cvta.to.shared.u64 t, %1; cvt.u32.u64 %0, t; }"
        : "=r"(a) : "l"(p));
    return a;
}
__device__ __forceinline__ void ldsm_x4(uint32_t& r0, uint32_t& r1,
                                        uint32_t& r2, uint32_t& r3, uint32_t a) {
    asm volatile("ldmatrix.sync.aligned.m8n8.x4.shared.b16 {%0,%1,%2,%3}, [%4];"
                 : "=r"(r0), "=r"(r1), "=r"(r2), "=r"(r3) : "r"(a));
}
__device__ __forceinline__ void mma16816(float* d, const uint32_t* a,
                                         uint32_t b0, uint32_t b1) {
    asm volatile(
        "mma.sync.aligned.m16n8k16.row.col.f32.bf16.bf16.f32 "
        "{%0,%1,%2,%3}, {%4,%5,%6,%7}, {%8,%9}, {%0,%1,%2,%3};"
        : "+f"(d[0]), "+f"(d[1]), "+f"(d[2]), "+f"(d[3])
        : "r"(a[0]), "r"(a[1]), "r"(a[2]), "r"(a[3]), "r"(b0), "r"(b1));
}
__device__ __forceinline__ uint32_t sw_off(int R, int c) {
    return (uint32_t)(R * 128 + ((c ^ (R & 7)) << 4));
}
__device__ __forceinline__ void cp16(uint32_t s, const void* g) {
    asm volatile("cp.async.cg.shared.global [%0], [%1], 16;" :: "r"(s), "l"(g));
}

// Grid barrier: all PGRID blocks co-resident.
__device__ __forceinline__ void grid_barrier(int tid, unsigned target) {
    __syncthreads();
    if (tid == 0) {
        __threadfence();
        atomicAdd(&g_bar, 1u);
        while (*((volatile unsigned*)&g_bar) < target) { }
        __threadfence();
    }
    __syncthreads();
}

__global__ __launch_bounds__(256, 2) void fused_kernel(const float* __restrict__ emb,
                                                       const int* __restrict__ lab,
                                                       float* __restrict__ out) {
    __shared__ __align__(16) __nv_bfloat16 Asm[3][BM * CH];   // 3 x 16KB
    __shared__ __align__(16) __nv_bfloat16 Bsm[3][BM * CH];   // 3 x 16KB
    __shared__ int   lrow[3][BM], lcol[3][BM];
    __shared__ float prowf[3][BM], pcol[3][BM];
    __shared__ float swcls[BATCH * 16];   // per-class weights 1/cnt
    __shared__ int   tinfo[MAXT];
    __shared__ float red[8];
    __shared__ int   hist[16];

    const int tid = threadIdx.x;
    const int wid = tid >> 5;
    const int lid = tid & 31;
    const int wr  = wid & 1;
    const int wc  = wid >> 1;
    const int bid = blockIdx.x;

    // ====== Phase A: histogram (7-tile blocks only) + convert ===============
    if (bid >= HIST0) {
        if (tid < 16) hist[tid] = 0;
        __syncthreads();
        const int h  = bid - HIST0;          // 0..63
        const int b  = h >> 4;               // 16 blocks per batch
        const int p0 = (h & 15) * 256;
        atomicAdd(&hist[lab[b * NPIX + p0 + tid] & 15], 1);
        __syncthreads();
        if (tid < 16 && hist[tid] > 0) atomicAdd(&g_cnt[b * 16 + tid], hist[tid]);
    }
    for (int q = bid * 256 + tid; q < NQ; q += PGRID * 256) {
        const int c4 = (q & 15) * 4;
        const int n  = (q >> 4) & (NPIX - 1);
        const float4 v = reinterpret_cast<const float4*>(emb)[q];
        const int chunk = c4 >> 3;
        const int dcol  = ((chunk ^ (n & 7)) << 3) + (c4 & 7);
        __nv_bfloat162 p0(__float2bfloat16(v.x), __float2bfloat16(v.y));
        __nv_bfloat162 p1(__float2bfloat16(v.z), __float2bfloat16(v.w));
        uint2 pk;
        pk.x = *reinterpret_cast<uint32_t*>(&p0);
        pk.y = *reinterpret_cast<uint32_t*>(&p1);
        *reinterpret_cast<uint2*>(g_ebf + ((size_t)(q >> 4)) * CH + dcol) = pk;
    }
    grid_barrier(tid, PGRID);

    // per-class weight table (bit-identical to 1.0f/(float)cnt)
    if (tid < BATCH * 16) {
        const int c = g_cnt[tid];
        swcls[tid] = (c > 0) ? (1.0f / (float)c) : 0.0f;
    }
    __syncthreads();

    // ====== Phase C: HMMA Gram (R10/R13 verbatim) ===========================
    const uint32_t aS[3] = { smem_u32(Asm[0]), smem_u32(Asm[1]), smem_u32(Asm[2]) };
    const uint32_t bS[3] = { smem_u32(Bsm[0]), smem_u32(Bsm[1]), smem_u32(Bsm[2]) };

    const int nt = (NTILES - bid + PGRID - 1) / PGRID;

    if (tid == 0) {
        for (int k = 0; k < nt; k++) {
            const int idx = bid + k * PGRID;
            const int b = idx / TRI;
            int t = idx - b * TRI;
            int u = 0;
            while (t >= TILES - u) { t -= TILES - u; u++; }
            tinfo[k] = (b << 12) | (u << 6) | (u + t);
        }
    }
    __syncthreads();

    auto issue = [&](int k, int buf) {
        const int inf = tinfo[k];
        const int b = inf >> 12, ti = (inf >> 6) & 63, tj = inf & 63;
        const int row0 = ti * BM, col0 = tj * BM;
        const char* srcA = (const char*)(g_ebf + ((size_t)(b * NPIX + row0)) * CH);
        const char* srcB = (const char*)(g_ebf + ((size_t)(b * NPIX + col0)) * CH);
#pragma unroll
        for (int p = 0; p < 4; p++) {
            const int o = (tid + 256 * p) * 16;
            cp16(aS[buf] + o, srcA + o);
            cp16(bS[buf] + o, srcB + o);
        }
        if (tid < BM) {
            const int l = lab[b * NPIX + row0 + tid] & 15;
            lrow[buf][tid]  = l;
            prowf[buf][tid] = (ti == tj ? 1.0f : 2.0f) * swcls[(b << 4) + l];
        } else {
            const int u = tid - BM;
            const int l = lab[b * NPIX + col0 + u] & 15;
            lcol[buf][u] = l;
            pcol[buf][u] = swcls[(b << 4) + l];
        }
        asm volatile("cp.async.commit_group;" ::: "memory");
    };

    float tsum = 0.0f;
    issue(0, 0);
    if (nt > 1) issue(1, 1);

    int buf = 0, nbuf = 2;
    for (int k = 0; k < nt; k++) {
        if (k + 1 < nt) asm volatile("cp.async.wait_group 1;" ::: "memory");
        else            asm volatile("cp.async.wait_group 0;" ::: "memory");
        __syncthreads();
        if (k + 2 < nt) issue(k + 2, nbuf);

        const int inf = tinfo[k];
        const int ti = (inf >> 6) & 63, tj = inf & 63;
        const bool diag = (ti == tj);

        const uint32_t a_base = aS[buf];
        const uint32_t b_base = bS[buf];

        float acc[4][4][4];
#pragma unroll
        for (int i = 0; i < 4; i++)
#pragma unroll
            for (int j = 0; j < 4; j++)
#pragma unroll
                for (int e = 0; e < 4; e++) acc[i][j][e] = 0.0f;

        const int aR = 64 * wr + (lid & 15);
        const int bR = 32 * wc + (lid & 15);
        const int hi = lid >> 4;

#pragma unroll
        for (int ks = 0; ks < 4; ks++) {
            const int ck = ks * 2 + hi;
            uint32_t a[4][4];
#pragma unroll
            for (int i = 0; i < 4; i++) {
                const int R = aR + 16 * i;
                ldsm_x4(a[i][0], a[i][1], a[i][2], a[i][3], a_base + sw_off(R, ck));
            }
            uint32_t bb[2][4];
#pragma unroll
            for (int p = 0; p < 2; p++) {
                const int R = bR + 16 * p;
                ldsm_x4(bb[p][0], bb[p][1], bb[p][2], bb[p][3], b_base + sw_off(R, ck));
            }
#pragma unroll
            for (int i = 0; i < 4; i++)
#pragma unroll
                for (int j = 0; j < 4; j++)
                    mma16816(acc[i][j], a[i], bb[j >> 1][j & 1], bb[j >> 1][(j & 1) + 2]);
        }

        const int gr = lid >> 2;
        const int qc = (lid & 3) * 2;
        if (!diag) {
#pragma unroll
            for (int i = 0; i < 4; i++) {
                const int rl0 = 64 * wr + 16 * i + gr, rl1 = rl0 + 8;
                const int  ln0 = lrow[buf][rl0], ln1 = lrow[buf][rl1];
                float rs0 = 0.0f, rs1 = 0.0f;
#pragma unroll
                for (int j = 0; j < 4; j++) {
                    const int cl = 32 * wc + 8 * j + qc;
                    const int  lc0 = lcol[buf][cl],  lc1 = lcol[buf][cl + 1];
                    const float pc0 = pcol[buf][cl], pc1 = pcol[buf][cl + 1];
                    const float s0 = acc[i][j][0], s1 = acc[i][j][1];
                    const float s2 = acc[i][j][2], s3 = acc[i][j][3];
                    const float v0 = (ln0 == lc0) ? (1.0f - s0) : fmaxf(s0 - MARGIN, 0.0f);
                    const float v1 = (ln0 == lc1) ? (1.0f - s1) : fmaxf(s1 - MARGIN, 0.0f);
                    const float v2 = (ln1 == lc0) ? (1.0f - s2) : fmaxf(s2 - MARGIN, 0.0f);
                    const float v3 = (ln1 == lc1) ? (1.0f - s3) : fmaxf(s3 - MARGIN, 0.0f);
                    rs0 = fmaf(v0, pc0, rs0); rs0 = fmaf(v1, pc1, rs0);
                    rs1 = fmaf(v2, pc0, rs1); rs1 = fmaf(v3, pc1, rs1);
                }
                tsum = fmaf(rs0, prowf[buf][rl0], tsum);
                tsum = fmaf(rs1, prowf[buf][rl1], tsum);
            }
        } else {
#pragma unroll
            for (int i = 0; i < 4; i++) {
#pragma unroll
                for (int j = 0; j < 4; j++) {
                    const int cl = 32 * wc + 8 * j + qc;
#pragma unroll
                    for (int e = 0; e < 4; e++) {
                        const int rl = 64 * wr + 16 * i + gr + ((e >> 1) << 3);
                        const int cc = cl + (e & 1);
                        const float s = acc[i][j][e];
                        const float v = (lrow[buf][rl] == lcol[buf][cc])
                                          ? (1.0f - s) : fmaxf(s - MARGIN, 0.0f);
                        float w = 2.0f * prowf[buf][rl] * pcol[buf][cc];
                        if (cc == rl)     w *= 0.5f;
                        else if (cc < rl) w = 0.0f;
                        tsum = fmaf(v, w, tsum);
                    }
                }
            }
        }
        buf  = (buf  == 2) ? 0 : buf + 1;
        nbuf = (nbuf == 2) ? 0 : nbuf + 1;
    }

    // ---- block reduce; last block finalizes and resets state ---------------
#pragma unroll
    for (int o = 16; o > 0; o >>= 1)
        tsum += __shfl_xor_sync(0xffffffffu, tsum, o);
    if (lid == 0) red[wid] = tsum;
    __syncthreads();
    if (tid == 0) {
        float bsum = 0.0f;
#pragma unroll
        for (int wv = 0; wv < 8; wv++) bsum += red[wv];
        atomicAdd(&g_acc, (double)bsum);
        __threadfence();
        const unsigned done = atomicAdd(&g_done, 1u);
        if (done == (unsigned)(PGRID - 1)) {
            __threadfence();
            out[0] = (float)(*((volatile double*)&g_acc) * (double)NPIX);
            g_acc  = 0.0;
            g_done = 0u;
            g_bar  = 0u;
#pragma unroll
            for (int i = 0; i < BATCH * 16; i++) g_cnt[i] = 0;
            __threadfence();
        }
    }
}

extern "C" void kernel_launch(void* const* d_in, const int* in_sizes, int n_in,
                              void* d_out, int out_size) {
    const float* emb = (const float*)d_in[0];
    const int*   lab = (const int*)d_in[1];
    float* out = (float*)d_out;

    fused_kernel<<<PGRID, 256>>>(emb, lab, out);
}